// round 12
// baseline (speedup 1.0000x reference)
#include <cuda_runtime.h>
#include <cuda_fp16.h>
#include <cstdint>

// Problem dims (fixed by the reference)
#define QN   512
#define CN   512
#define TNT  128
#define DIN  512
#define DHD  256
#define KCORR (TNT * DHD)   // 32768
#define MAXLAG 4
#define NLAG  9             // lags -4..4
#define MROWS (QN * TNT)    // 65536

// ---------------------------------------------------------------------------
// Scratch (static device globals; no allocation allowed)
// ---------------------------------------------------------------------------
__device__ __half g_Hh [MROWS * DHD];   // hidden fp16 (reused audio/video)
__device__ __half g_Ahf[MROWS * DHD];   // audio features fp16  [Q, T*DH]
__device__ __half g_Phf[MROWS * DHD];   // projected video fp16 [C, T*DH]
__device__ float g_Wc[DHD * DHD];       // folded v_w2 @ W (fp32)
__device__ float g_bc[DHD];             // folded v_b2 @ W
// pre-converted, pre-transposed weights: [N][K], K contiguous (fp16)
__device__ __half g_W1ah[DHD * DIN];
__device__ __half g_W1vh[DHD * DIN];
__device__ __half g_W2ah[DHD * DHD];
__device__ __half g_Wcth[DHD * DHD];
__device__ unsigned g_Smax[QN * CN];    // encoded max-over-lags scores

// ---------------------------------------------------------------------------
// Portable PTX helpers (valid on compute_103 virtual target)
// ---------------------------------------------------------------------------
__device__ __forceinline__ uint32_t smem_u32(const void* p) {
    uint32_t a;
    asm("{ .reg .u64 t; cvta.to.shared.u64 t, %1; cvt.u32.u64 %0, t; }"
        : "=r"(a) : "l"(p));
    return a;
}

#define CP_ASYNC_16(dst, src) \
    asm volatile("cp.async.ca.shared.global [%0], [%1], 16;" \
        :: "r"(dst), "l"(src) : "memory")
#define CP_ASYNC_CG_16(dst, src) \
    asm volatile("cp.async.cg.shared.global [%0], [%1], 16;" \
        :: "r"(dst), "l"(src) : "memory")
#define CP_ASYNC_COMMIT() asm volatile("cp.async.commit_group;" ::: "memory")
#define CP_ASYNC_WAIT_1() asm volatile("cp.async.wait_group 1;" ::: "memory")
#define CP_ASYNC_WAIT_0() asm volatile("cp.async.wait_group 0;" ::: "memory")

#define LDSM_X4(r, addr) \
    asm volatile("ldmatrix.sync.aligned.m8n8.x4.shared.b16 {%0,%1,%2,%3}, [%4];" \
        : "=r"((r)[0]), "=r"((r)[1]), "=r"((r)[2]), "=r"((r)[3]) : "r"(addr))

__device__ __forceinline__ void mma_f16(float* c, const uint32_t* a,
                                        const uint32_t* b) {
    asm volatile(
        "mma.sync.aligned.m16n8k16.row.col.f32.f16.f16.f32 "
        "{%0,%1,%2,%3}, {%4,%5,%6,%7}, {%8,%9}, {%0,%1,%2,%3};"
        : "+f"(c[0]), "+f"(c[1]), "+f"(c[2]), "+f"(c[3])
        : "r"(a[0]), "r"(a[1]), "r"(a[2]), "r"(a[3]), "r"(b[0]), "r"(b[1]));
}

// monotonic fp32 <-> uint encoding for atomicMax
__device__ __forceinline__ unsigned enc_f32(float f) {
    unsigned u = __float_as_uint(f);
    return (u & 0x80000000u) ? ~u : (u | 0x80000000u);
}
__device__ __forceinline__ float dec_f32(unsigned u) {
    return (u & 0x80000000u) ? __uint_as_float(u ^ 0x80000000u)
                             : __uint_as_float(~u);
}

// ---------------------------------------------------------------------------
// Prep: fold v_w2 @ W -> g_Wc, g_bc
// ---------------------------------------------------------------------------
__global__ void prep_w_kernel(const float* __restrict__ v_w2,
                              const float* __restrict__ v_b2,
                              const float* __restrict__ W) {
    int i = blockIdx.x;
    int j = threadIdx.x;
    float acc = 0.f;
    #pragma unroll 8
    for (int k = 0; k < DHD; ++k)
        acc += v_w2[i * DHD + k] * W[k * DHD + j];
    g_Wc[i * DHD + j] = acc;
    if (i == 0) {
        float accb = 0.f;
        #pragma unroll 8
        for (int k = 0; k < DHD; ++k)
            accb += v_b2[k] * W[k * DHD + j];
        g_bc[j] = accb;
    }
}

// Prep: batched transpose+convert fp32 [K,256] -> fp16 [256][K] for 4 arrays,
// plus reset of the encoded score buffer (blockIdx.y == 4).
__global__ void convt_all_kernel(const float* __restrict__ s0, __half* d0, int K0,
                                 const float* __restrict__ s1, __half* d1, int K1,
                                 const float* __restrict__ s2, __half* d2, int K2,
                                 const float* __restrict__ s3, __half* d3, int K3) {
    int which = blockIdx.y;
    if (which == 4) {   // reset g_Smax (encoded -inf = 0)
        int idx = blockIdx.x * blockDim.x + threadIdx.x;
        for (; idx < QN * CN; idx += gridDim.x * blockDim.x)
            g_Smax[idx] = 0u;
        return;
    }
    const float* in; __half* oh; int K;
    if (which == 0)      { in = s0; oh = d0; K = K0; }
    else if (which == 1) { in = s1; oh = d1; K = K1; }
    else if (which == 2) { in = s2; oh = d2; K = K2; }
    else                 { in = s3; oh = d3; K = K3; }
    int n = blockIdx.x;
    for (int k = threadIdx.x; k < K; k += blockDim.x)
        oh[(size_t)n * K + k] = __float2half_rn(in[(size_t)k * DHD + n]);
}

// ---------------------------------------------------------------------------
// MLP tiling constants (2 tiles: A, B) — R11-proven
// ---------------------------------------------------------------------------
#define BKC     32                  // K elems per chunk (MLP)
#define ROWB    80                  // padded row stride bytes (64 data + 16)
#define TILE_PB (128 * ROWB)        // 10240
#define BUF_PB  (2 * TILE_PB)       // A, B = 20480
#define HMMA_SMEM (2 * BUF_PB)      // 40960

extern __shared__ char dsm[];

// ---------------------------------------------------------------------------
// MLP GEMM on HMMA, pure fp16 (R11-proven)
// ---------------------------------------------------------------------------
template <bool CONVERT_A, bool RELU>
__global__ __launch_bounds__(256, 1)
void mlp_hmma_kernel(const float* __restrict__ Af,
                     const __half* __restrict__ Ag,
                     const __half* __restrict__ Bh,
                     const float* __restrict__ bias,
                     __half* __restrict__ Oh,
                     int K) {
    const uint32_t sb = smem_u32(dsm);
    const int tid  = threadIdx.x;
    const int wid  = tid >> 5;
    const int lane = tid & 31;
    const int bm = blockIdx.x * 128;
    const int bn = blockIdx.y * 128;
    const int NCH = K / BKC;

    const int wm = (wid >> 2) * 64;
    const int wn = (wid & 3) * 32;

    float acc[4][4][4];
    #pragma unroll
    for (int mi = 0; mi < 4; ++mi)
        #pragma unroll
        for (int nf = 0; nf < 4; ++nf)
            #pragma unroll
            for (int r = 0; r < 4; ++r) acc[mi][nf][r] = 0.f;

    const int aRow = wm + (lane & 15);
    const int aSeg = (lane >> 4) << 4;
    const int bg   = lane >> 3;
    const int bRow = wn + ((bg >> 1) << 3) + (lane & 7);
    const int bSeg = (bg & 1) << 4;

    float4 areg[4];

    auto prefetch_B = [&](int c, int buf) {
        const int k0 = c * BKC;
        const uint32_t base = sb + buf * BUF_PB;
        #pragma unroll
        for (int i = 0; i < 2; ++i) {
            int u = tid + i * 256;
            int row = u >> 2, seg = u & 3;
            uint32_t dst = base + 1 * TILE_PB + row * ROWB + seg * 16;
            const __half* src = Bh + (size_t)(bn + row) * K + k0 + seg * 8;
            CP_ASYNC_16(dst, src);
        }
    };
    auto prefetch_A_f16 = [&](int c, int buf) {
        const int k0 = c * BKC;
        const uint32_t base = sb + buf * BUF_PB;
        #pragma unroll
        for (int i = 0; i < 2; ++i) {
            int u = tid + i * 256;
            int row = u >> 2, seg = u & 3;
            uint32_t dst = base + row * ROWB + seg * 16;
            const __half* src = Ag + (size_t)(bm + row) * K + k0 + seg * 8;
            CP_ASYNC_16(dst, src);
        }
    };
    auto ldg_A_f32 = [&](int c) {
        const int k0 = c * BKC;
        #pragma unroll
        for (int i = 0; i < 4; ++i) {
            int s = tid + i * 256;
            int row = s >> 3, seg = s & 7;
            areg[i] = *(const float4*)&Af[(size_t)(bm + row) * K + k0 + seg * 4];
        }
    };
    auto sts_A_cvt = [&](int buf) {
        const uint32_t base = sb + buf * BUF_PB;
        #pragma unroll
        for (int i = 0; i < 4; ++i) {
            int s = tid + i * 256;
            int row = s >> 3, seg = s & 7;
            uint32_t off = row * ROWB + seg * 8;
            float4 v = areg[i];
            __half2 h01 = __halves2half2(__float2half_rn(v.x), __float2half_rn(v.y));
            __half2 h23 = __halves2half2(__float2half_rn(v.z), __float2half_rn(v.w));
            uint32_t hu0 = *(uint32_t*)&h01, hu1 = *(uint32_t*)&h23;
            asm volatile("st.shared.v2.b32 [%0], {%1, %2};"
                         :: "r"(base + off), "r"(hu0), "r"(hu1) : "memory");
        }
    };

    if (CONVERT_A) {
        ldg_A_f32(0);
        prefetch_B(0, 0);
        CP_ASYNC_COMMIT();
    } else {
        prefetch_A_f16(0, 0);
        prefetch_B(0, 0);
        CP_ASYNC_COMMIT();
    }

    for (int c = 0; c < NCH; ++c) {
        const int buf = c & 1;
        if (CONVERT_A) {
            sts_A_cvt(buf);
            if (c + 1 < NCH) {
                prefetch_B(c + 1, buf ^ 1);
                CP_ASYNC_COMMIT();
                CP_ASYNC_WAIT_1();
            } else {
                CP_ASYNC_WAIT_0();
            }
            __syncthreads();
            if (c + 1 < NCH) ldg_A_f32(c + 1);
        } else {
            if (c + 1 < NCH) {
                prefetch_A_f16(c + 1, buf ^ 1);
                prefetch_B(c + 1, buf ^ 1);
                CP_ASYNC_COMMIT();
                CP_ASYNC_WAIT_1();
            } else {
                CP_ASYNC_WAIT_0();
            }
            __syncthreads();
        }

        const uint32_t tb  = sb + buf * BUF_PB;
        const uint32_t ahB = tb;
        const uint32_t bhB = tb + 1 * TILE_PB;

        #pragma unroll
        for (int ks = 0; ks < 2; ++ks) {
            const int kbyte = ks * 32;
            uint32_t ah[4][4], ph[4][2];
            #pragma unroll
            for (int mi = 0; mi < 4; ++mi) {
                uint32_t off = (uint32_t)(aRow + mi * 16) * ROWB + kbyte + aSeg;
                LDSM_X4(ah[mi], ahB + off);
            }
            #pragma unroll
            for (int ni = 0; ni < 2; ++ni) {
                uint32_t off = (uint32_t)(bRow + ni * 16) * ROWB + kbyte + bSeg;
                uint32_t r[4];
                LDSM_X4(r, bhB + off);
                ph[2 * ni][0] = r[0]; ph[2 * ni][1] = r[1];
                ph[2 * ni + 1][0] = r[2]; ph[2 * ni + 1][1] = r[3];
            }
            #pragma unroll
            for (int mi = 0; mi < 4; ++mi)
                #pragma unroll
                for (int nf = 0; nf < 4; ++nf)
                    mma_f16(acc[mi][nf], ah[mi], ph[nf]);
        }
        __syncthreads();
    }

    #pragma unroll
    for (int mi = 0; mi < 4; ++mi) {
        int r0 = bm + wm + mi * 16 + (lane >> 2);
        #pragma unroll
        for (int nf = 0; nf < 4; ++nf) {
            int cn = bn + wn + nf * 8 + 2 * (lane & 3);
            float b0 = bias[cn], b1 = bias[cn + 1];
            #pragma unroll
            for (int half_ = 0; half_ < 2; ++half_) {
                int r = r0 + half_ * 8;
                float o0 = acc[mi][nf][2 * half_ + 0] + b0;
                float o1 = acc[mi][nf][2 * half_ + 1] + b1;
                if (RELU) { o0 = fmaxf(o0, 0.f); o1 = fmaxf(o1, 0.f); }
                __half2 hh = __halves2half2(__float2half_rn(o0),
                                            __float2half_rn(o1));
                *(__half2*)&Oh[(size_t)r * DHD + cn] = hh;
            }
        }
    }
}

// ---------------------------------------------------------------------------
// Correlation v6: single fp16 term; 128x64 tiles, 256 threads, 2 CTAs/SM
//   (4 warps/SMSP from independent sync domains). 8 warps as 4x2, warp tile
//   32x32, BKC=64, 2-stage cp.async. grid (4, 8, 9) = 288 CTAs.
//   Epilogue: fused max-over-lags via encoded atomicMax.
// ---------------------------------------------------------------------------
#define BKC6     64
#define NCH6     (KCORR / BKC6)      // 512
#define ROW6     144                 // 128B data + 16 pad
#define TA6      (128 * ROW6)        // A tile: 18432
#define TP6      (64 * ROW6)         // P tile: 9216
#define BUF6     (TA6 + TP6)         // 27648
#define CORR_SMEM (2 * BUF6)         // 55296

__device__ __forceinline__ void corr_prefetch6(
    uint32_t sb, int buf, int c, int bm, int bn, int lag,
    const __half* __restrict__ Ah, const __half* __restrict__ Ph, int tid)
{
    const int k0 = c * BKC6;
    const int t  = c >> 2;                       // k0 / 256
    const int d0 = (c & 3) << 6;                 // k0 % 256
    const int ts = (t + lag + TNT) & (TNT - 1);
    const int kb = ts * DHD + d0;

    const uint32_t base = sb + buf * BUF6;
    #pragma unroll
    for (int i = 0; i < 6; ++i) {
        int u = tid + i * 256;                   // 0..1535
        uint32_t dst;
        const __half* src;
        if (u < 1024) {                          // A: 128 rows x 8 segs
            int row = u >> 3, seg = u & 7;
            dst = base + row * ROW6 + seg * 16;
            src = Ah + (size_t)(bm + row) * KCORR + k0 + seg * 8;
        } else {                                 // P: 64 rows x 8 segs
            int w = u - 1024;
            int row = w >> 3, seg = w & 7;
            dst = base + TA6 + row * ROW6 + seg * 16;
            src = Ph + (size_t)(bn + row) * KCORR + kb + seg * 8;
        }
        CP_ASYNC_CG_16(dst, src);
    }
    CP_ASYNC_COMMIT();
}

__global__ __launch_bounds__(256, 2)
void corr_hmma_kernel(const __half* __restrict__ Ah,
                      const __half* __restrict__ Ph) {
    const uint32_t sb = smem_u32(dsm);
    const int tid  = threadIdx.x;
    const int wid  = tid >> 5;
    const int lane = tid & 31;
    const int bm = blockIdx.x * 128;             // q tile (128)
    const int bn = blockIdx.y * 64;              // c tile (64)
    const int lag = (int)blockIdx.z - MAXLAG;

    const int wm = (wid >> 1) * 32;              // 0,32,64,96
    const int wn = (wid & 1) * 32;               // 0,32

    float acc[2][4][4];
    #pragma unroll
    for (int mi = 0; mi < 2; ++mi)
        #pragma unroll
        for (int nf = 0; nf < 4; ++nf)
            #pragma unroll
            for (int r = 0; r < 4; ++r) acc[mi][nf][r] = 0.f;

    const int aRow = wm + (lane & 15);
    const int aSeg = (lane >> 4) << 4;
    const int bg   = lane >> 3;
    const int bRow = wn + ((bg >> 1) << 3) + (lane & 7);
    const int bSeg = (bg & 1) << 4;

    // register ks double-buffer
    uint32_t fah[2][2][4], fbh[2][4][2];

    corr_prefetch6(sb, 0, 0, bm, bn, lag, Ah, Ph, tid);

    for (int c = 0; c < NCH6; ++c) {
        const int buf = c & 1;
        if (c + 1 < NCH6) {
            corr_prefetch6(sb, buf ^ 1, c + 1, bm, bn, lag, Ah, Ph, tid);
            CP_ASYNC_WAIT_1();
        } else {
            CP_ASYNC_WAIT_0();
        }
        __syncthreads();

        const uint32_t ahB = sb + buf * BUF6;
        const uint32_t phB = ahB + TA6;

        // load fragments for ks = 0
        #pragma unroll
        for (int mi = 0; mi < 2; ++mi) {
            uint32_t off = (uint32_t)(aRow + mi * 16) * ROW6 + aSeg;
            LDSM_X4(fah[0][mi], ahB + off);
        }
        #pragma unroll
        for (int ni = 0; ni < 2; ++ni) {
            uint32_t off = (uint32_t)(bRow + ni * 16) * ROW6 + bSeg;
            uint32_t r[4];
            LDSM_X4(r, phB + off);
            fbh[0][2 * ni][0] = r[0]; fbh[0][2 * ni][1] = r[1];
            fbh[0][2 * ni + 1][0] = r[2]; fbh[0][2 * ni + 1][1] = r[3];
        }

        #pragma unroll
        for (int ks = 0; ks < 4; ++ks) {
            const int cur = ks & 1;
            if (ks < 3) {
                const int nxt = cur ^ 1;
                const int kbyte = (ks + 1) * 32;
                #pragma unroll
                for (int mi = 0; mi < 2; ++mi) {
                    uint32_t off = (uint32_t)(aRow + mi * 16) * ROW6 + kbyte + aSeg;
                    LDSM_X4(fah[nxt][mi], ahB + off);
                }
                #pragma unroll
                for (int ni = 0; ni < 2; ++ni) {
                    uint32_t off = (uint32_t)(bRow + ni * 16) * ROW6 + kbyte + bSeg;
                    uint32_t r[4];
                    LDSM_X4(r, phB + off);
                    fbh[nxt][2 * ni][0] = r[0]; fbh[nxt][2 * ni][1] = r[1];
                    fbh[nxt][2 * ni + 1][0] = r[2]; fbh[nxt][2 * ni + 1][1] = r[3];
                }
            }
            #pragma unroll
            for (int mi = 0; mi < 2; ++mi)
                #pragma unroll
                for (int nf = 0; nf < 4; ++nf)
                    mma_f16(acc[mi][nf], fah[cur][mi], fbh[cur][nf]);
        }
        __syncthreads();
    }

    // Epilogue: fused max over lags via encoded atomicMax
    #pragma unroll
    for (int mi = 0; mi < 2; ++mi) {
        int r0 = bm + wm + mi * 16 + (lane >> 2);
        #pragma unroll
        for (int nf = 0; nf < 4; ++nf) {
            int col = bn + wn + nf * 8 + 2 * (lane & 3);
            atomicMax(&g_Smax[(size_t)r0 * CN + col],       enc_f32(acc[mi][nf][0]));
            atomicMax(&g_Smax[(size_t)r0 * CN + col + 1],   enc_f32(acc[mi][nf][1]));
            atomicMax(&g_Smax[(size_t)(r0 + 8) * CN + col],     enc_f32(acc[mi][nf][2]));
            atomicMax(&g_Smax[(size_t)(r0 + 8) * CN + col + 1], enc_f32(acc[mi][nf][3]));
        }
    }
}

// ---------------------------------------------------------------------------
// Decode encoded maxima -> fp32 output
// ---------------------------------------------------------------------------
__global__ void decode_kernel(float* __restrict__ out) {
    int idx = blockIdx.x * blockDim.x + threadIdx.x;
    out[idx] = dec_f32(g_Smax[idx]);
}

// ---------------------------------------------------------------------------
// Launch
// ---------------------------------------------------------------------------
extern "C" void kernel_launch(void* const* d_in, const int* in_sizes, int n_in,
                              void* d_out, int out_size) {
    const float* audio = (const float*)d_in[0];
    const float* video = (const float*)d_in[1];
    const float* a_w1  = (const float*)d_in[2];
    const float* a_b1  = (const float*)d_in[3];
    const float* a_w2  = (const float*)d_in[4];
    const float* a_b2  = (const float*)d_in[5];
    const float* v_w1  = (const float*)d_in[6];
    const float* v_b1  = (const float*)d_in[7];
    const float* v_w2  = (const float*)d_in[8];
    const float* v_b2  = (const float*)d_in[9];
    const float* W     = (const float*)d_in[10];
    float* out = (float*)d_out;

    float *gWc, *gbc;
    __half *gHh, *gAhf, *gPhf;
    __half *gW1ah, *gW1vh, *gW2ah, *gWcth;
    cudaGetSymbolAddress((void**)&gHh,  g_Hh);
    cudaGetSymbolAddress((void**)&gAhf, g_Ahf);
    cudaGetSymbolAddress((void**)&gPhf, g_Phf);
    cudaGetSymbolAddress((void**)&gWc, g_Wc);
    cudaGetSymbolAddress((void**)&gbc, g_bc);
    cudaGetSymbolAddress((void**)&gW1ah, g_W1ah);
    cudaGetSymbolAddress((void**)&gW1vh, g_W1vh);
    cudaGetSymbolAddress((void**)&gW2ah, g_W2ah);
    cudaGetSymbolAddress((void**)&gWcth, g_Wcth);

    cudaFuncSetAttribute(corr_hmma_kernel,
                         cudaFuncAttributeMaxDynamicSharedMemorySize, CORR_SMEM);
    cudaFuncSetAttribute(mlp_hmma_kernel<true, true>,
                         cudaFuncAttributeMaxDynamicSharedMemorySize, HMMA_SMEM);
    cudaFuncSetAttribute(mlp_hmma_kernel<false, false>,
                         cudaFuncAttributeMaxDynamicSharedMemorySize, HMMA_SMEM);

    // 0) prep: fold Wc, then one batched convert (+ g_Smax reset in same grid)
    prep_w_kernel<<<DHD, DHD>>>(v_w2, v_b2, W);
    convt_all_kernel<<<dim3(DHD, 5), 256>>>(
        a_w1, gW1ah, DIN,
        v_w1, gW1vh, DIN,
        a_w2, gW2ah, DHD,
        gWc,  gWcth, DHD);

    const dim3 mlp_grid(MROWS / 128, DHD / 128);   // 512 x 2

    // 1) audio MLP on HMMA (pure fp16)
    mlp_hmma_kernel<true,  true ><<<mlp_grid, 256, HMMA_SMEM>>>(
        audio, nullptr, gW1ah, a_b1, gHh, DIN);
    mlp_hmma_kernel<false, false><<<mlp_grid, 256, HMMA_SMEM>>>(
        nullptr, gHh, gW2ah, a_b2, gAhf, DHD);

    // 2) video MLP + folded projection on HMMA (pure fp16)
    mlp_hmma_kernel<true,  true ><<<mlp_grid, 256, HMMA_SMEM>>>(
        video, nullptr, gW1vh, v_b1, gHh, DIN);
    mlp_hmma_kernel<false, false><<<mlp_grid, 256, HMMA_SMEM>>>(
        nullptr, gHh, gWcth, gbc, gPhf, DHD);

    // 3) per-lag correlation: 128x64 tiles, 288 CTAs, 2 CTAs/SM,
    //    fused max-over-lags via atomicMax
    corr_hmma_kernel<<<dim3(QN / 128, CN / 64, NLAG), 256, CORR_SMEM>>>(
        gAhf, gPhf);

    // 4) decode encoded maxima into the output
    decode_kernel<<<(QN * CN) / 256, 256>>>(out);
}

// round 13
// speedup vs baseline: 1.2184x; 1.2184x over previous
#include <cuda_runtime.h>
#include <cuda_fp16.h>
#include <cstdint>

// Problem dims (fixed by the reference)
#define QN   512
#define CN   512
#define TNT  128
#define DIN  512
#define DHD  256
#define KCORR (TNT * DHD)   // 32768
#define MAXLAG 4
#define NLAG  9             // lags -4..4
#define MROWS (QN * TNT)    // 65536

// ---------------------------------------------------------------------------
// Scratch (static device globals; no allocation allowed)
// ---------------------------------------------------------------------------
__device__ __half g_Hh [MROWS * DHD];   // hidden fp16 (reused audio/video)
__device__ __half g_Ahf[MROWS * DHD];   // audio features fp16  [Q, T*DH]
__device__ __half g_Phf[MROWS * DHD];   // projected video fp16 [C, T*DH]
__device__ float g_Wc[DHD * DHD];       // folded v_w2 @ W (fp32)
__device__ float g_bc[DHD];             // folded v_b2 @ W
// pre-converted, pre-transposed weights: [N][K], K contiguous (fp16)
__device__ __half g_W1ah[DHD * DIN];
__device__ __half g_W1vh[DHD * DIN];
__device__ __half g_W2ah[DHD * DHD];
__device__ __half g_Wcth[DHD * DHD];
__device__ unsigned g_Smax[QN * CN];    // encoded max-over-lags scores

// ---------------------------------------------------------------------------
// Portable PTX helpers (valid on compute_103 virtual target)
// ---------------------------------------------------------------------------
__device__ __forceinline__ uint32_t smem_u32(const void* p) {
    uint32_t a;
    asm("{ .reg .u64 t; cvta.to.shared.u64 t, %1; cvt.u32.u64 %0, t; }"
        : "=r"(a) : "l"(p));
    return a;
}

#define CP_ASYNC_16(dst, src) \
    asm volatile("cp.async.ca.shared.global [%0], [%1], 16;" \
        :: "r"(dst), "l"(src) : "memory")
#define CP_ASYNC_CG_16(dst, src) \
    asm volatile("cp.async.cg.shared.global [%0], [%1], 16;" \
        :: "r"(dst), "l"(src) : "memory")
#define CP_ASYNC_COMMIT() asm volatile("cp.async.commit_group;" ::: "memory")
#define CP_ASYNC_WAIT_1() asm volatile("cp.async.wait_group 1;" ::: "memory")
#define CP_ASYNC_WAIT_0() asm volatile("cp.async.wait_group 0;" ::: "memory")

#define LDSM_X4(r, addr) \
    asm volatile("ldmatrix.sync.aligned.m8n8.x4.shared.b16 {%0,%1,%2,%3}, [%4];" \
        : "=r"((r)[0]), "=r"((r)[1]), "=r"((r)[2]), "=r"((r)[3]) : "r"(addr))

__device__ __forceinline__ void mma_f16(float* c, const uint32_t* a,
                                        const uint32_t* b) {
    asm volatile(
        "mma.sync.aligned.m16n8k16.row.col.f32.f16.f16.f32 "
        "{%0,%1,%2,%3}, {%4,%5,%6,%7}, {%8,%9}, {%0,%1,%2,%3};"
        : "+f"(c[0]), "+f"(c[1]), "+f"(c[2]), "+f"(c[3])
        : "r"(a[0]), "r"(a[1]), "r"(a[2]), "r"(a[3]), "r"(b[0]), "r"(b[1]));
}

// monotonic fp32 <-> uint encoding for atomicMax
__device__ __forceinline__ unsigned enc_f32(float f) {
    unsigned u = __float_as_uint(f);
    return (u & 0x80000000u) ? ~u : (u | 0x80000000u);
}
__device__ __forceinline__ float dec_f32(unsigned u) {
    return (u & 0x80000000u) ? __uint_as_float(u ^ 0x80000000u)
                             : __uint_as_float(~u);
}

// ---------------------------------------------------------------------------
// Prep: fold v_w2 @ W -> g_Wc, g_bc
// ---------------------------------------------------------------------------
__global__ void prep_w_kernel(const float* __restrict__ v_w2,
                              const float* __restrict__ v_b2,
                              const float* __restrict__ W) {
    int i = blockIdx.x;
    int j = threadIdx.x;
    float acc = 0.f;
    #pragma unroll 8
    for (int k = 0; k < DHD; ++k)
        acc += v_w2[i * DHD + k] * W[k * DHD + j];
    g_Wc[i * DHD + j] = acc;
    if (i == 0) {
        float accb = 0.f;
        #pragma unroll 8
        for (int k = 0; k < DHD; ++k)
            accb += v_b2[k] * W[k * DHD + j];
        g_bc[j] = accb;
    }
}

// Prep: batched transpose+convert fp32 [K,256] -> fp16 [256][K] for 4 arrays,
// plus reset of the encoded score buffer (blockIdx.y == 4).
__global__ void convt_all_kernel(const float* __restrict__ s0, __half* d0, int K0,
                                 const float* __restrict__ s1, __half* d1, int K1,
                                 const float* __restrict__ s2, __half* d2, int K2,
                                 const float* __restrict__ s3, __half* d3, int K3) {
    int which = blockIdx.y;
    if (which == 4) {   // reset g_Smax (encoded -inf = 0)
        int idx = blockIdx.x * blockDim.x + threadIdx.x;
        for (; idx < QN * CN; idx += gridDim.x * blockDim.x)
            g_Smax[idx] = 0u;
        return;
    }
    const float* in; __half* oh; int K;
    if (which == 0)      { in = s0; oh = d0; K = K0; }
    else if (which == 1) { in = s1; oh = d1; K = K1; }
    else if (which == 2) { in = s2; oh = d2; K = K2; }
    else                 { in = s3; oh = d3; K = K3; }
    int n = blockIdx.x;
    for (int k = threadIdx.x; k < K; k += blockDim.x)
        oh[(size_t)n * K + k] = __float2half_rn(in[(size_t)k * DHD + n]);
}

// ---------------------------------------------------------------------------
// MLP tiling constants (2 tiles: A, B)
// ---------------------------------------------------------------------------
#define BKC     32                  // K elems per chunk (MLP)
#define ROWB    80                  // padded row stride bytes (64 data + 16)
#define TILE_PB (128 * ROWB)        // 10240
#define BUF_PB  (2 * TILE_PB)       // A, B = 20480
#define HMMA_SMEM (2 * BUF_PB)      // 40960

extern __shared__ char dsm[];

// ---------------------------------------------------------------------------
// MLP GEMM on HMMA, pure fp16. 256 threads, 128x128 tile, 2 CTAs/SM
//   (launch_bounds(256,2) caps regs at 128 -> fixes occ=12.3% from R12 ncu).
// ---------------------------------------------------------------------------
template <bool CONVERT_A, bool RELU>
__global__ __launch_bounds__(256, 2)
void mlp_hmma_kernel(const float* __restrict__ Af,
                     const __half* __restrict__ Ag,
                     const __half* __restrict__ Bh,
                     const float* __restrict__ bias,
                     __half* __restrict__ Oh,
                     int K) {
    const uint32_t sb = smem_u32(dsm);
    const int tid  = threadIdx.x;
    const int wid  = tid >> 5;
    const int lane = tid & 31;
    const int bm = blockIdx.x * 128;
    const int bn = blockIdx.y * 128;
    const int NCH = K / BKC;

    const int wm = (wid >> 2) * 64;
    const int wn = (wid & 3) * 32;

    float acc[4][4][4];
    #pragma unroll
    for (int mi = 0; mi < 4; ++mi)
        #pragma unroll
        for (int nf = 0; nf < 4; ++nf)
            #pragma unroll
            for (int r = 0; r < 4; ++r) acc[mi][nf][r] = 0.f;

    const int aRow = wm + (lane & 15);
    const int aSeg = (lane >> 4) << 4;
    const int bg   = lane >> 3;
    const int bRow = wn + ((bg >> 1) << 3) + (lane & 7);
    const int bSeg = (bg & 1) << 4;

    float4 areg[4];

    auto prefetch_B = [&](int c, int buf) {
        const int k0 = c * BKC;
        const uint32_t base = sb + buf * BUF_PB;
        #pragma unroll
        for (int i = 0; i < 2; ++i) {
            int u = tid + i * 256;
            int row = u >> 2, seg = u & 3;
            uint32_t dst = base + 1 * TILE_PB + row * ROWB + seg * 16;
            const __half* src = Bh + (size_t)(bn + row) * K + k0 + seg * 8;
            CP_ASYNC_16(dst, src);
        }
    };
    auto prefetch_A_f16 = [&](int c, int buf) {
        const int k0 = c * BKC;
        const uint32_t base = sb + buf * BUF_PB;
        #pragma unroll
        for (int i = 0; i < 2; ++i) {
            int u = tid + i * 256;
            int row = u >> 2, seg = u & 3;
            uint32_t dst = base + row * ROWB + seg * 16;
            const __half* src = Ag + (size_t)(bm + row) * K + k0 + seg * 8;
            CP_ASYNC_16(dst, src);
        }
    };
    auto ldg_A_f32 = [&](int c) {
        const int k0 = c * BKC;
        #pragma unroll
        for (int i = 0; i < 4; ++i) {
            int s = tid + i * 256;
            int row = s >> 3, seg = s & 7;
            areg[i] = *(const float4*)&Af[(size_t)(bm + row) * K + k0 + seg * 4];
        }
    };
    auto sts_A_cvt = [&](int buf) {
        const uint32_t base = sb + buf * BUF_PB;
        #pragma unroll
        for (int i = 0; i < 4; ++i) {
            int s = tid + i * 256;
            int row = s >> 3, seg = s & 7;
            uint32_t off = row * ROWB + seg * 8;
            float4 v = areg[i];
            __half2 h01 = __halves2half2(__float2half_rn(v.x), __float2half_rn(v.y));
            __half2 h23 = __halves2half2(__float2half_rn(v.z), __float2half_rn(v.w));
            uint32_t hu0 = *(uint32_t*)&h01, hu1 = *(uint32_t*)&h23;
            asm volatile("st.shared.v2.b32 [%0], {%1, %2};"
                         :: "r"(base + off), "r"(hu0), "r"(hu1) : "memory");
        }
    };

    if (CONVERT_A) {
        ldg_A_f32(0);
        prefetch_B(0, 0);
        CP_ASYNC_COMMIT();
    } else {
        prefetch_A_f16(0, 0);
        prefetch_B(0, 0);
        CP_ASYNC_COMMIT();
    }

    for (int c = 0; c < NCH; ++c) {
        const int buf = c & 1;
        if (CONVERT_A) {
            sts_A_cvt(buf);
            if (c + 1 < NCH) {
                prefetch_B(c + 1, buf ^ 1);
                CP_ASYNC_COMMIT();
                CP_ASYNC_WAIT_1();
            } else {
                CP_ASYNC_WAIT_0();
            }
            __syncthreads();
            if (c + 1 < NCH) ldg_A_f32(c + 1);
        } else {
            if (c + 1 < NCH) {
                prefetch_A_f16(c + 1, buf ^ 1);
                prefetch_B(c + 1, buf ^ 1);
                CP_ASYNC_COMMIT();
                CP_ASYNC_WAIT_1();
            } else {
                CP_ASYNC_WAIT_0();
            }
            __syncthreads();
        }

        const uint32_t tb  = sb + buf * BUF_PB;
        const uint32_t ahB = tb;
        const uint32_t bhB = tb + 1 * TILE_PB;

        #pragma unroll
        for (int ks = 0; ks < 2; ++ks) {
            const int kbyte = ks * 32;
            uint32_t ah[4][4], ph[4][2];
            #pragma unroll
            for (int mi = 0; mi < 4; ++mi) {
                uint32_t off = (uint32_t)(aRow + mi * 16) * ROWB + kbyte + aSeg;
                LDSM_X4(ah[mi], ahB + off);
            }
            #pragma unroll
            for (int ni = 0; ni < 2; ++ni) {
                uint32_t off = (uint32_t)(bRow + ni * 16) * ROWB + kbyte + bSeg;
                uint32_t r[4];
                LDSM_X4(r, bhB + off);
                ph[2 * ni][0] = r[0]; ph[2 * ni][1] = r[1];
                ph[2 * ni + 1][0] = r[2]; ph[2 * ni + 1][1] = r[3];
            }
            #pragma unroll
            for (int mi = 0; mi < 4; ++mi)
                #pragma unroll
                for (int nf = 0; nf < 4; ++nf)
                    mma_f16(acc[mi][nf], ah[mi], ph[nf]);
        }
        __syncthreads();
    }

    #pragma unroll
    for (int mi = 0; mi < 4; ++mi) {
        int r0 = bm + wm + mi * 16 + (lane >> 2);
        #pragma unroll
        for (int nf = 0; nf < 4; ++nf) {
            int cn = bn + wn + nf * 8 + 2 * (lane & 3);
            float b0 = bias[cn], b1 = bias[cn + 1];
            #pragma unroll
            for (int half_ = 0; half_ < 2; ++half_) {
                int r = r0 + half_ * 8;
                float o0 = acc[mi][nf][2 * half_ + 0] + b0;
                float o1 = acc[mi][nf][2 * half_ + 1] + b1;
                if (RELU) { o0 = fmaxf(o0, 0.f); o1 = fmaxf(o1, 0.f); }
                __half2 hh = __halves2half2(__float2half_rn(o0),
                                            __float2half_rn(o1));
                *(__half2*)&Oh[(size_t)r * DHD + cn] = hh;
            }
        }
    }
}

// ---------------------------------------------------------------------------
// Correlation v5 (R9/R11-proven): SINGLE fp16 term.
//   128x128 tile, 256 threads, 8 warps, warp tile 64x32, BKC=128 (8 k16
//   steps), register ks double-buffer, 2-stage cp.async. 144 CTAs, one wave.
//   Epilogue (R13): fused max-over-lags via encoded atomicMax.
// ---------------------------------------------------------------------------
#define BKC5     128
#define NCH5     (KCORR / BKC5)      // 256
#define ROW5     272                 // 256B data + 16 pad
#define TILE5    (128 * ROW5)        // 34816
#define BUF5     (2 * TILE5)         // A, P = 69632
#define CORR_SMEM (2 * BUF5)         // 139264

__device__ __forceinline__ void corr_prefetch5(
    uint32_t sb, int buf, int c, int bm, int bn, int lag,
    const __half* __restrict__ Ah, const __half* __restrict__ Ph, int tid)
{
    const int k0 = c * BKC5;
    const int t  = c >> 1;                       // k0 / 256
    const int d0 = (c & 1) << 7;                 // k0 % 256
    const int ts = (t + lag + TNT) & (TNT - 1);
    const int kb = ts * DHD + d0;

    const uint32_t base = sb + buf * BUF5;
    #pragma unroll
    for (int i = 0; i < 16; ++i) {
        int u    = tid + i * 256;                // 0..4095
        int tile = u >> 11;                      // 0..1
        int w    = u & 2047;
        int row  = w >> 4;                       // 0..127
        int seg  = w & 15;                       // 16B segment
        uint32_t dst = base + tile * TILE5 + row * ROW5 + seg * 16;
        const __half* src = (tile == 0)
            ? Ah + (size_t)(bm + row) * KCORR + k0 + seg * 8
            : Ph + (size_t)(bn + row) * KCORR + kb + seg * 8;
        CP_ASYNC_CG_16(dst, src);
    }
    CP_ASYNC_COMMIT();
}

__global__ __launch_bounds__(256, 1)
void corr_hmma_kernel(const __half* __restrict__ Ah,
                      const __half* __restrict__ Ph) {
    const uint32_t sb = smem_u32(dsm);
    const int tid  = threadIdx.x;
    const int wid  = tid >> 5;
    const int lane = tid & 31;
    const int bm = blockIdx.x * 128;
    const int bn = blockIdx.y * 128;
    const int lag = (int)blockIdx.z - MAXLAG;

    const int wm = (wid >> 2) * 64;              // 0, 64
    const int wn = (wid & 3) * 32;               // 0,32,64,96

    float acc[4][4][4];
    #pragma unroll
    for (int mi = 0; mi < 4; ++mi)
        #pragma unroll
        for (int nf = 0; nf < 4; ++nf)
            #pragma unroll
            for (int r = 0; r < 4; ++r) acc[mi][nf][r] = 0.f;

    const int aRow = wm + (lane & 15);
    const int aSeg = (lane >> 4) << 4;
    const int bg   = lane >> 3;
    const int bRow = wn + ((bg >> 1) << 3) + (lane & 7);
    const int bSeg = (bg & 1) << 4;

    // register ks double-buffer
    uint32_t fah[2][4][4], fbh[2][4][2];

    corr_prefetch5(sb, 0, 0, bm, bn, lag, Ah, Ph, tid);

    for (int c = 0; c < NCH5; ++c) {
        const int buf = c & 1;
        if (c + 1 < NCH5) {
            corr_prefetch5(sb, buf ^ 1, c + 1, bm, bn, lag, Ah, Ph, tid);
            CP_ASYNC_WAIT_1();
        } else {
            CP_ASYNC_WAIT_0();
        }
        __syncthreads();

        const uint32_t tb  = sb + buf * BUF5;
        const uint32_t ahB = tb + 0 * TILE5;
        const uint32_t phB = tb + 1 * TILE5;

        // load fragments for ks = 0
        #pragma unroll
        for (int mi = 0; mi < 4; ++mi) {
            uint32_t off = (uint32_t)(aRow + mi * 16) * ROW5 + aSeg;
            LDSM_X4(fah[0][mi], ahB + off);
        }
        #pragma unroll
        for (int ni = 0; ni < 2; ++ni) {
            uint32_t off = (uint32_t)(bRow + ni * 16) * ROW5 + bSeg;
            uint32_t r[4];
            LDSM_X4(r, phB + off);
            fbh[0][2 * ni][0] = r[0]; fbh[0][2 * ni][1] = r[1];
            fbh[0][2 * ni + 1][0] = r[2]; fbh[0][2 * ni + 1][1] = r[3];
        }

        #pragma unroll
        for (int ks = 0; ks < 8; ++ks) {
            const int cur = ks & 1;
            if (ks < 7) {
                const int nxt = cur ^ 1;
                const int kbyte = (ks + 1) * 32;
                #pragma unroll
                for (int mi = 0; mi < 4; ++mi) {
                    uint32_t off = (uint32_t)(aRow + mi * 16) * ROW5 + kbyte + aSeg;
                    LDSM_X4(fah[nxt][mi], ahB + off);
                }
                #pragma unroll
                for (int ni = 0; ni < 2; ++ni) {
                    uint32_t off = (uint32_t)(bRow + ni * 16) * ROW5 + kbyte + bSeg;
                    uint32_t r[4];
                    LDSM_X4(r, phB + off);
                    fbh[nxt][2 * ni][0] = r[0]; fbh[nxt][2 * ni][1] = r[1];
                    fbh[nxt][2 * ni + 1][0] = r[2]; fbh[nxt][2 * ni + 1][1] = r[3];
                }
            }
            #pragma unroll
            for (int mi = 0; mi < 4; ++mi)
                #pragma unroll
                for (int nf = 0; nf < 4; ++nf)
                    mma_f16(acc[mi][nf], fah[cur][mi], fbh[cur][nf]);
        }
        __syncthreads();
    }

    // Epilogue: fused max over lags via encoded atomicMax
    #pragma unroll
    for (int mi = 0; mi < 4; ++mi) {
        int r0 = bm + wm + mi * 16 + (lane >> 2);
        #pragma unroll
        for (int nf = 0; nf < 4; ++nf) {
            int col = bn + wn + nf * 8 + 2 * (lane & 3);
            atomicMax(&g_Smax[(size_t)r0 * CN + col],           enc_f32(acc[mi][nf][0]));
            atomicMax(&g_Smax[(size_t)r0 * CN + col + 1],       enc_f32(acc[mi][nf][1]));
            atomicMax(&g_Smax[(size_t)(r0 + 8) * CN + col],     enc_f32(acc[mi][nf][2]));
            atomicMax(&g_Smax[(size_t)(r0 + 8) * CN + col + 1], enc_f32(acc[mi][nf][3]));
        }
    }
}

// ---------------------------------------------------------------------------
// Decode encoded maxima -> fp32 output
// ---------------------------------------------------------------------------
__global__ void decode_kernel(float* __restrict__ out) {
    int idx = blockIdx.x * blockDim.x + threadIdx.x;
    out[idx] = dec_f32(g_Smax[idx]);
}

// ---------------------------------------------------------------------------
// Launch
// ---------------------------------------------------------------------------
extern "C" void kernel_launch(void* const* d_in, const int* in_sizes, int n_in,
                              void* d_out, int out_size) {
    const float* audio = (const float*)d_in[0];
    const float* video = (const float*)d_in[1];
    const float* a_w1  = (const float*)d_in[2];
    const float* a_b1  = (const float*)d_in[3];
    const float* a_w2  = (const float*)d_in[4];
    const float* a_b2  = (const float*)d_in[5];
    const float* v_w1  = (const float*)d_in[6];
    const float* v_b1  = (const float*)d_in[7];
    const float* v_w2  = (const float*)d_in[8];
    const float* v_b2  = (const float*)d_in[9];
    const float* W     = (const float*)d_in[10];
    float* out = (float*)d_out;

    float *gWc, *gbc;
    __half *gHh, *gAhf, *gPhf;
    __half *gW1ah, *gW1vh, *gW2ah, *gWcth;
    cudaGetSymbolAddress((void**)&gHh,  g_Hh);
    cudaGetSymbolAddress((void**)&gAhf, g_Ahf);
    cudaGetSymbolAddress((void**)&gPhf, g_Phf);
    cudaGetSymbolAddress((void**)&gWc, g_Wc);
    cudaGetSymbolAddress((void**)&gbc, g_bc);
    cudaGetSymbolAddress((void**)&gW1ah, g_W1ah);
    cudaGetSymbolAddress((void**)&gW1vh, g_W1vh);
    cudaGetSymbolAddress((void**)&gW2ah, g_W2ah);
    cudaGetSymbolAddress((void**)&gWcth, g_Wcth);

    cudaFuncSetAttribute(corr_hmma_kernel,
                         cudaFuncAttributeMaxDynamicSharedMemorySize, CORR_SMEM);
    cudaFuncSetAttribute(mlp_hmma_kernel<true, true>,
                         cudaFuncAttributeMaxDynamicSharedMemorySize, HMMA_SMEM);
    cudaFuncSetAttribute(mlp_hmma_kernel<false, false>,
                         cudaFuncAttributeMaxDynamicSharedMemorySize, HMMA_SMEM);

    // 0) prep: fold Wc, then one batched convert (+ g_Smax reset in same grid)
    prep_w_kernel<<<DHD, DHD>>>(v_w2, v_b2, W);
    convt_all_kernel<<<dim3(DHD, 5), 256>>>(
        a_w1, gW1ah, DIN,
        v_w1, gW1vh, DIN,
        a_w2, gW2ah, DHD,
        gWc,  gWcth, DHD);

    const dim3 mlp_grid(MROWS / 128, DHD / 128);   // 512 x 2

    // 1) audio MLP on HMMA (pure fp16, 2 CTAs/SM)
    mlp_hmma_kernel<true,  true ><<<mlp_grid, 256, HMMA_SMEM>>>(
        audio, nullptr, gW1ah, a_b1, gHh, DIN);
    mlp_hmma_kernel<false, false><<<mlp_grid, 256, HMMA_SMEM>>>(
        nullptr, gHh, gW2ah, a_b2, gAhf, DHD);

    // 2) video MLP + folded projection on HMMA (pure fp16, 2 CTAs/SM)
    mlp_hmma_kernel<true,  true ><<<mlp_grid, 256, HMMA_SMEM>>>(
        video, nullptr, gW1vh, v_b1, gHh, DIN);
    mlp_hmma_kernel<false, false><<<mlp_grid, 256, HMMA_SMEM>>>(
        nullptr, gHh, gWcth, gbc, gPhf, DHD);

    // 3) per-lag correlation: R11-proven v5 + fused max-over-lags
    corr_hmma_kernel<<<dim3(QN / 128, CN / 128, NLAG), 256, CORR_SMEM>>>(
        gAhf, gPhf);

    // 4) decode encoded maxima into the output
    decode_kernel<<<(QN * CN) / 256, 256>>>(out);
}

// round 14
// speedup vs baseline: 1.3494x; 1.1076x over previous
#include <cuda_runtime.h>
#include <cuda_fp16.h>
#include <cstdint>

// Problem dims (fixed by the reference)
#define QN   512
#define CN   512
#define TNT  128
#define DIN  512
#define DHD  256
#define KCORR (TNT * DHD)   // 32768
#define MAXLAG 4
#define NLAG  9             // lags -4..4
#define MROWS (QN * TNT)    // 65536

// ---------------------------------------------------------------------------
// Scratch (static device globals; no allocation allowed)
// ---------------------------------------------------------------------------
__device__ __half g_Hha[MROWS * DHD];   // audio hidden fp16
__device__ __half g_Hhv[MROWS * DHD];   // video hidden fp16
__device__ __half g_Ahf[MROWS * DHD];   // audio features fp16  [Q, T*DH]
__device__ __half g_Phf[MROWS * DHD];   // projected video fp16 [C, T*DH]
__device__ float g_Wc[DHD * DHD];       // folded v_w2 @ W (fp32)
__device__ float g_bc[DHD];             // folded v_b2 @ W
// pre-converted, pre-transposed weights: [N][K], K contiguous (fp16)
__device__ __half g_W1ah[DHD * DIN];
__device__ __half g_W1vh[DHD * DIN];
__device__ __half g_W2ah[DHD * DHD];
__device__ __half g_Wcth[DHD * DHD];
__device__ float g_Sp[NLAG * QN * CN];  // per-lag scores (atomicAdd partials)

// ---------------------------------------------------------------------------
// Portable PTX helpers (valid on compute_103 virtual target)
// ---------------------------------------------------------------------------
__device__ __forceinline__ uint32_t smem_u32(const void* p) {
    uint32_t a;
    asm("{ .reg .u64 t; cvta.to.shared.u64 t, %1; cvt.u32.u64 %0, t; }"
        : "=r"(a) : "l"(p));
    return a;
}

#define CP_ASYNC_16(dst, src) \
    asm volatile("cp.async.ca.shared.global [%0], [%1], 16;" \
        :: "r"(dst), "l"(src) : "memory")
#define CP_ASYNC_CG_16(dst, src) \
    asm volatile("cp.async.cg.shared.global [%0], [%1], 16;" \
        :: "r"(dst), "l"(src) : "memory")
#define CP_ASYNC_COMMIT() asm volatile("cp.async.commit_group;" ::: "memory")
#define CP_ASYNC_WAIT_1() asm volatile("cp.async.wait_group 1;" ::: "memory")
#define CP_ASYNC_WAIT_0() asm volatile("cp.async.wait_group 0;" ::: "memory")

#define LDSM_X4(r, addr) \
    asm volatile("ldmatrix.sync.aligned.m8n8.x4.shared.b16 {%0,%1,%2,%3}, [%4];" \
        : "=r"((r)[0]), "=r"((r)[1]), "=r"((r)[2]), "=r"((r)[3]) : "r"(addr))

__device__ __forceinline__ void mma_f16(float* c, const uint32_t* a,
                                        const uint32_t* b) {
    asm volatile(
        "mma.sync.aligned.m16n8k16.row.col.f32.f16.f16.f32 "
        "{%0,%1,%2,%3}, {%4,%5,%6,%7}, {%8,%9}, {%0,%1,%2,%3};"
        : "+f"(c[0]), "+f"(c[1]), "+f"(c[2]), "+f"(c[3])
        : "r"(a[0]), "r"(a[1]), "r"(a[2]), "r"(a[3]), "r"(b[0]), "r"(b[1]));
}

// ---------------------------------------------------------------------------
// Prep: fold v_w2 @ W -> g_Wc, g_bc
// ---------------------------------------------------------------------------
__global__ void prep_w_kernel(const float* __restrict__ v_w2,
                              const float* __restrict__ v_b2,
                              const float* __restrict__ W) {
    int i = blockIdx.x;
    int j = threadIdx.x;
    float acc = 0.f;
    #pragma unroll 8
    for (int k = 0; k < DHD; ++k)
        acc += v_w2[i * DHD + k] * W[k * DHD + j];
    g_Wc[i * DHD + j] = acc;
    if (i == 0) {
        float accb = 0.f;
        #pragma unroll 8
        for (int k = 0; k < DHD; ++k)
            accb += v_b2[k] * W[k * DHD + j];
        g_bc[j] = accb;
    }
}

// Prep: batched transpose+convert fp32 [K,256] -> fp16 [256][K] for 4 arrays,
// plus reset of g_Sp (blockIdx.y == 4).
__global__ void convt_all_kernel(const float* __restrict__ s0, __half* d0, int K0,
                                 const float* __restrict__ s1, __half* d1, int K1,
                                 const float* __restrict__ s2, __half* d2, int K2,
                                 const float* __restrict__ s3, __half* d3, int K3) {
    int which = blockIdx.y;
    if (which == 4) {   // reset g_Sp to 0
        int idx = blockIdx.x * blockDim.x + threadIdx.x;
        for (; idx < NLAG * QN * CN; idx += gridDim.x * blockDim.x)
            g_Sp[idx] = 0.f;
        return;
    }
    const float* in; __half* oh; int K;
    if (which == 0)      { in = s0; oh = d0; K = K0; }
    else if (which == 1) { in = s1; oh = d1; K = K1; }
    else if (which == 2) { in = s2; oh = d2; K = K2; }
    else                 { in = s3; oh = d3; K = K3; }
    int n = blockIdx.x;
    for (int k = threadIdx.x; k < K; k += blockDim.x)
        oh[(size_t)n * K + k] = __float2half_rn(in[(size_t)k * DHD + n]);
}

// ---------------------------------------------------------------------------
// MLP tiling constants (2 tiles: A, B)
// ---------------------------------------------------------------------------
#define BKC     32                  // K elems per chunk (MLP)
#define ROWB    80                  // padded row stride bytes (64 data + 16)
#define TILE_PB (128 * ROWB)        // 10240
#define BUF_PB  (2 * TILE_PB)       // A, B = 20480
#define HMMA_SMEM (2 * BUF_PB)      // 40960

extern __shared__ char dsm[];

// ---------------------------------------------------------------------------
// MLP GEMM on HMMA, pure fp16, batched over audio/video via blockIdx.z.
// 256 threads, 128x128 tile, 2 CTAs/SM (R13-proven).
// ---------------------------------------------------------------------------
template <bool CONVERT_A, bool RELU>
__global__ __launch_bounds__(256, 2)
void mlp_hmma_kernel(const float* __restrict__ Af0,
                     const __half* __restrict__ Ag0,
                     const __half* __restrict__ Bh0,
                     const float* __restrict__ bias0,
                     __half* __restrict__ Oh0,
                     const float* __restrict__ Af1,
                     const __half* __restrict__ Ag1,
                     const __half* __restrict__ Bh1,
                     const float* __restrict__ bias1,
                     __half* __restrict__ Oh1,
                     int K) {
    const float*  Af   = blockIdx.z ? Af1   : Af0;
    const __half* Ag   = blockIdx.z ? Ag1   : Ag0;
    const __half* Bh   = blockIdx.z ? Bh1   : Bh0;
    const float*  bias = blockIdx.z ? bias1 : bias0;
    __half*       Oh   = blockIdx.z ? Oh1   : Oh0;

    const uint32_t sb = smem_u32(dsm);
    const int tid  = threadIdx.x;
    const int wid  = tid >> 5;
    const int lane = tid & 31;
    const int bm = blockIdx.x * 128;
    const int bn = blockIdx.y * 128;
    const int NCH = K / BKC;

    const int wm = (wid >> 2) * 64;
    const int wn = (wid & 3) * 32;

    float acc[4][4][4];
    #pragma unroll
    for (int mi = 0; mi < 4; ++mi)
        #pragma unroll
        for (int nf = 0; nf < 4; ++nf)
            #pragma unroll
            for (int r = 0; r < 4; ++r) acc[mi][nf][r] = 0.f;

    const int aRow = wm + (lane & 15);
    const int aSeg = (lane >> 4) << 4;
    const int bg   = lane >> 3;
    const int bRow = wn + ((bg >> 1) << 3) + (lane & 7);
    const int bSeg = (bg & 1) << 4;

    float4 areg[4];

    auto prefetch_B = [&](int c, int buf) {
        const int k0 = c * BKC;
        const uint32_t base = sb + buf * BUF_PB;
        #pragma unroll
        for (int i = 0; i < 2; ++i) {
            int u = tid + i * 256;
            int row = u >> 2, seg = u & 3;
            uint32_t dst = base + 1 * TILE_PB + row * ROWB + seg * 16;
            const __half* src = Bh + (size_t)(bn + row) * K + k0 + seg * 8;
            CP_ASYNC_16(dst, src);
        }
    };
    auto prefetch_A_f16 = [&](int c, int buf) {
        const int k0 = c * BKC;
        const uint32_t base = sb + buf * BUF_PB;
        #pragma unroll
        for (int i = 0; i < 2; ++i) {
            int u = tid + i * 256;
            int row = u >> 2, seg = u & 3;
            uint32_t dst = base + row * ROWB + seg * 16;
            const __half* src = Ag + (size_t)(bm + row) * K + k0 + seg * 8;
            CP_ASYNC_16(dst, src);
        }
    };
    auto ldg_A_f32 = [&](int c) {
        const int k0 = c * BKC;
        #pragma unroll
        for (int i = 0; i < 4; ++i) {
            int s = tid + i * 256;
            int row = s >> 3, seg = s & 7;
            areg[i] = *(const float4*)&Af[(size_t)(bm + row) * K + k0 + seg * 4];
        }
    };
    auto sts_A_cvt = [&](int buf) {
        const uint32_t base = sb + buf * BUF_PB;
        #pragma unroll
        for (int i = 0; i < 4; ++i) {
            int s = tid + i * 256;
            int row = s >> 3, seg = s & 7;
            uint32_t off = row * ROWB + seg * 8;
            float4 v = areg[i];
            __half2 h01 = __halves2half2(__float2half_rn(v.x), __float2half_rn(v.y));
            __half2 h23 = __halves2half2(__float2half_rn(v.z), __float2half_rn(v.w));
            uint32_t hu0 = *(uint32_t*)&h01, hu1 = *(uint32_t*)&h23;
            asm volatile("st.shared.v2.b32 [%0], {%1, %2};"
                         :: "r"(base + off), "r"(hu0), "r"(hu1) : "memory");
        }
    };

    if (CONVERT_A) {
        ldg_A_f32(0);
        prefetch_B(0, 0);
        CP_ASYNC_COMMIT();
    } else {
        prefetch_A_f16(0, 0);
        prefetch_B(0, 0);
        CP_ASYNC_COMMIT();
    }

    for (int c = 0; c < NCH; ++c) {
        const int buf = c & 1;
        if (CONVERT_A) {
            sts_A_cvt(buf);
            if (c + 1 < NCH) {
                prefetch_B(c + 1, buf ^ 1);
                CP_ASYNC_COMMIT();
                CP_ASYNC_WAIT_1();
            } else {
                CP_ASYNC_WAIT_0();
            }
            __syncthreads();
            if (c + 1 < NCH) ldg_A_f32(c + 1);
        } else {
            if (c + 1 < NCH) {
                prefetch_A_f16(c + 1, buf ^ 1);
                prefetch_B(c + 1, buf ^ 1);
                CP_ASYNC_COMMIT();
                CP_ASYNC_WAIT_1();
            } else {
                CP_ASYNC_WAIT_0();
            }
            __syncthreads();
        }

        const uint32_t tb  = sb + buf * BUF_PB;
        const uint32_t ahB = tb;
        const uint32_t bhB = tb + 1 * TILE_PB;

        #pragma unroll
        for (int ks = 0; ks < 2; ++ks) {
            const int kbyte = ks * 32;
            uint32_t ah[4][4], ph[4][2];
            #pragma unroll
            for (int mi = 0; mi < 4; ++mi) {
                uint32_t off = (uint32_t)(aRow + mi * 16) * ROWB + kbyte + aSeg;
                LDSM_X4(ah[mi], ahB + off);
            }
            #pragma unroll
            for (int ni = 0; ni < 2; ++ni) {
                uint32_t off = (uint32_t)(bRow + ni * 16) * ROWB + kbyte + bSeg;
                uint32_t r[4];
                LDSM_X4(r, bhB + off);
                ph[2 * ni][0] = r[0]; ph[2 * ni][1] = r[1];
                ph[2 * ni + 1][0] = r[2]; ph[2 * ni + 1][1] = r[3];
            }
            #pragma unroll
            for (int mi = 0; mi < 4; ++mi)
                #pragma unroll
                for (int nf = 0; nf < 4; ++nf)
                    mma_f16(acc[mi][nf], ah[mi], ph[nf]);
        }
        __syncthreads();
    }

    #pragma unroll
    for (int mi = 0; mi < 4; ++mi) {
        int r0 = bm + wm + mi * 16 + (lane >> 2);
        #pragma unroll
        for (int nf = 0; nf < 4; ++nf) {
            int cn = bn + wn + nf * 8 + 2 * (lane & 3);
            float b0 = bias[cn], b1 = bias[cn + 1];
            #pragma unroll
            for (int half_ = 0; half_ < 2; ++half_) {
                int r = r0 + half_ * 8;
                float o0 = acc[mi][nf][2 * half_ + 0] + b0;
                float o1 = acc[mi][nf][2 * half_ + 1] + b1;
                if (RELU) { o0 = fmaxf(o0, 0.f); o1 = fmaxf(o1, 0.f); }
                __half2 hh = __halves2half2(__float2half_rn(o0),
                                            __float2half_rn(o1));
                *(__half2*)&Oh[(size_t)r * DHD + cn] = hh;
            }
        }
    }
}

// ---------------------------------------------------------------------------
// Correlation v7: K-split x2 -> 288 CTAs = 2 CTAs/SM with the GOOD 128x128
//   tile. Each CTA covers K half = 16384 (256 chunks of BKC=64), accumulates
//   fp32, and atomicAdds its partial into g_Sp[lag]. No register ks-pipeline
//   (cross-CTA overlap covers LDSM latency); regs ~105 < 128 cap.
// ---------------------------------------------------------------------------
#define BKC7     64
#define KHALF    (KCORR / 2)         // 16384
#define NCH7     (KHALF / BKC7)      // 256
#define ROW7     144                 // 128B data + 16 pad
#define TILE7    (128 * ROW7)        // 18432
#define BUF7     (2 * TILE7)         // A, P = 36864
#define CORR_SMEM (2 * BUF7)         // 73728 (x2 CTAs = 147456 <= 227K)

__device__ __forceinline__ void corr_prefetch7(
    uint32_t sb, int buf, int kglob, int bm, int bn, int lag,
    const __half* __restrict__ Ah, const __half* __restrict__ Ph, int tid)
{
    const int t  = kglob >> 8;                   // / 256
    const int d0 = kglob & 255;
    const int ts = (t + lag + TNT) & (TNT - 1);
    const int kb = ts * DHD + d0;

    const uint32_t base = sb + buf * BUF7;
    #pragma unroll
    for (int i = 0; i < 8; ++i) {
        int u    = tid + i * 256;                // 0..2047
        int tile = u >> 10;                      // 0..1
        int w    = u & 1023;
        int row  = w >> 3;                       // 0..127
        int seg  = w & 7;                        // 16B segment
        uint32_t dst = base + tile * TILE7 + row * ROW7 + seg * 16;
        const __half* src = (tile == 0)
            ? Ah + (size_t)(bm + row) * KCORR + kglob + seg * 8
            : Ph + (size_t)(bn + row) * KCORR + kb + seg * 8;
        CP_ASYNC_CG_16(dst, src);
    }
    CP_ASYNC_COMMIT();
}

__global__ __launch_bounds__(256, 2)
void corr_hmma_kernel(const __half* __restrict__ Ah,
                      const __half* __restrict__ Ph) {
    const uint32_t sb = smem_u32(dsm);
    const int tid  = threadIdx.x;
    const int wid  = tid >> 5;
    const int lane = tid & 31;
    const int bm = blockIdx.x * 128;
    const int bn = blockIdx.y * 128;
    const int lagIdx = blockIdx.z >> 1;          // 0..8
    const int khalf  = blockIdx.z & 1;           // 0..1
    const int lag = lagIdx - MAXLAG;
    const int kbase = khalf * KHALF;

    const int wm = (wid >> 2) * 64;              // 0, 64
    const int wn = (wid & 3) * 32;               // 0,32,64,96

    float acc[4][4][4];
    #pragma unroll
    for (int mi = 0; mi < 4; ++mi)
        #pragma unroll
        for (int nf = 0; nf < 4; ++nf)
            #pragma unroll
            for (int r = 0; r < 4; ++r) acc[mi][nf][r] = 0.f;

    const int aRow = wm + (lane & 15);
    const int aSeg = (lane >> 4) << 4;
    const int bg   = lane >> 3;
    const int bRow = wn + ((bg >> 1) << 3) + (lane & 7);
    const int bSeg = (bg & 1) << 4;

    corr_prefetch7(sb, 0, kbase, bm, bn, lag, Ah, Ph, tid);

    for (int c = 0; c < NCH7; ++c) {
        const int buf = c & 1;
        if (c + 1 < NCH7) {
            corr_prefetch7(sb, buf ^ 1, kbase + (c + 1) * BKC7,
                           bm, bn, lag, Ah, Ph, tid);
            CP_ASYNC_WAIT_1();
        } else {
            CP_ASYNC_WAIT_0();
        }
        __syncthreads();

        const uint32_t ahB = sb + buf * BUF7;
        const uint32_t phB = ahB + TILE7;

        #pragma unroll
        for (int ks = 0; ks < 4; ++ks) {
            const int kbyte = ks * 32;
            uint32_t ah[4][4], ph[4][2];
            #pragma unroll
            for (int mi = 0; mi < 4; ++mi) {
                uint32_t off = (uint32_t)(aRow + mi * 16) * ROW7 + kbyte + aSeg;
                LDSM_X4(ah[mi], ahB + off);
            }
            #pragma unroll
            for (int ni = 0; ni < 2; ++ni) {
                uint32_t off = (uint32_t)(bRow + ni * 16) * ROW7 + kbyte + bSeg;
                uint32_t r[4];
                LDSM_X4(r, phB + off);
                ph[2 * ni][0] = r[0]; ph[2 * ni][1] = r[1];
                ph[2 * ni + 1][0] = r[2]; ph[2 * ni + 1][1] = r[3];
            }
            #pragma unroll
            for (int mi = 0; mi < 4; ++mi)
                #pragma unroll
                for (int nf = 0; nf < 4; ++nf)
                    mma_f16(acc[mi][nf], ah[mi], ph[nf]);
        }
        __syncthreads();
    }

    // Epilogue: atomicAdd fp32 partial into per-lag buffer
    float* Sz = g_Sp + (size_t)lagIdx * QN * CN;
    #pragma unroll
    for (int mi = 0; mi < 4; ++mi) {
        int r0 = bm + wm + mi * 16 + (lane >> 2);
        #pragma unroll
        for (int nf = 0; nf < 4; ++nf) {
            int col = bn + wn + nf * 8 + 2 * (lane & 3);
            atomicAdd(&Sz[(size_t)r0 * CN + col],           acc[mi][nf][0]);
            atomicAdd(&Sz[(size_t)r0 * CN + col + 1],       acc[mi][nf][1]);
            atomicAdd(&Sz[(size_t)(r0 + 8) * CN + col],     acc[mi][nf][2]);
            atomicAdd(&Sz[(size_t)(r0 + 8) * CN + col + 1], acc[mi][nf][3]);
        }
    }
}

// ---------------------------------------------------------------------------
// Final max over lags
// ---------------------------------------------------------------------------
__global__ void maxlag_kernel(float* __restrict__ out) {
    int idx = blockIdx.x * blockDim.x + threadIdx.x;
    float m = g_Sp[idx];
    #pragma unroll
    for (int j = 1; j < NLAG; ++j)
        m = fmaxf(m, g_Sp[(size_t)j * QN * CN + idx]);
    out[idx] = m;
}

// ---------------------------------------------------------------------------
// Launch
// ---------------------------------------------------------------------------
extern "C" void kernel_launch(void* const* d_in, const int* in_sizes, int n_in,
                              void* d_out, int out_size) {
    const float* audio = (const float*)d_in[0];
    const float* video = (const float*)d_in[1];
    const float* a_w1  = (const float*)d_in[2];
    const float* a_b1  = (const float*)d_in[3];
    const float* a_w2  = (const float*)d_in[4];
    const float* a_b2  = (const float*)d_in[5];
    const float* v_w1  = (const float*)d_in[6];
    const float* v_b1  = (const float*)d_in[7];
    const float* v_w2  = (const float*)d_in[8];
    const float* v_b2  = (const float*)d_in[9];
    const float* W     = (const float*)d_in[10];
    float* out = (float*)d_out;

    float *gWc, *gbc;
    __half *gHha, *gHhv, *gAhf, *gPhf;
    __half *gW1ah, *gW1vh, *gW2ah, *gWcth;
    cudaGetSymbolAddress((void**)&gHha, g_Hha);
    cudaGetSymbolAddress((void**)&gHhv, g_Hhv);
    cudaGetSymbolAddress((void**)&gAhf, g_Ahf);
    cudaGetSymbolAddress((void**)&gPhf, g_Phf);
    cudaGetSymbolAddress((void**)&gWc, g_Wc);
    cudaGetSymbolAddress((void**)&gbc, g_bc);
    cudaGetSymbolAddress((void**)&gW1ah, g_W1ah);
    cudaGetSymbolAddress((void**)&gW1vh, g_W1vh);
    cudaGetSymbolAddress((void**)&gW2ah, g_W2ah);
    cudaGetSymbolAddress((void**)&gWcth, g_Wcth);

    cudaFuncSetAttribute(corr_hmma_kernel,
                         cudaFuncAttributeMaxDynamicSharedMemorySize, CORR_SMEM);
    cudaFuncSetAttribute(mlp_hmma_kernel<true, true>,
                         cudaFuncAttributeMaxDynamicSharedMemorySize, HMMA_SMEM);
    cudaFuncSetAttribute(mlp_hmma_kernel<false, false>,
                         cudaFuncAttributeMaxDynamicSharedMemorySize, HMMA_SMEM);

    // 0) prep: fold Wc, then one batched convert (+ g_Sp reset in same grid)
    prep_w_kernel<<<DHD, DHD>>>(v_w2, v_b2, W);
    convt_all_kernel<<<dim3(DHD, 5), 256>>>(
        a_w1, gW1ah, DIN,
        v_w1, gW1vh, DIN,
        a_w2, gW2ah, DHD,
        gWc,  gWcth, DHD);

    const dim3 mlp_grid(MROWS / 128, DHD / 128, 2);   // 512 x 2 x {audio,video}

    // 1) layer 1 for BOTH streams in one launch (z selects stream)
    mlp_hmma_kernel<true, true><<<mlp_grid, 256, HMMA_SMEM>>>(
        audio, nullptr, gW1ah, a_b1, gHha,
        video, nullptr, gW1vh, v_b1, gHhv, DIN);

    // 2) layer 2 for BOTH streams in one launch
    mlp_hmma_kernel<false, false><<<mlp_grid, 256, HMMA_SMEM>>>(
        nullptr, gHha, gW2ah, a_b2, gAhf,
        nullptr, gHhv, gWcth, gbc, gPhf, DHD);

    // 3) per-lag correlation: K-split x2, 288 CTAs = 2 CTAs/SM
    corr_hmma_kernel<<<dim3(QN / 128, CN / 128, NLAG * 2), 256, CORR_SMEM>>>(
        gAhf, gPhf);

    // 4) max over lags
    maxlag_kernel<<<(QN * CN) / 256, 256>>>(out);
}